// round 13
// baseline (speedup 1.0000x reference)
#include <cuda_runtime.h>
#include <cstdint>

#define NN 10000
#define EE 400000
#define HH 128
#define TPAD 132
#define APAD 36
#define NB64 157   // ceil(NN/64)
#define NB128 79   // ceil(NN/128)
#define CNT_BLKS 1563
#define PLACE_BLKS 3125
#define EDGE_BLKS 1250

typedef unsigned long long u64;

// ---------------- device scratch ----------------
__device__ float g_h  [NN * HH];
__device__ float g_agg[NN * HH];   // Rmean
__device__ float g_P  [NN * HH];
__device__ float g_Q  [NN * HH];
__device__ float g_U  [NN * HH];   // h @ Wa_upd
__device__ float g_inv [NN];
__device__ float g_flag[NN];
__device__ int   g_cnt[NN];
__device__ int   g_off[NN];
__device__ int   g_cur[NN];
__device__ float4 g_rec[EE];
__device__ float g_Wc[4][HH * HH];
__device__ float g_bc[4][HH];

// ---------------- packed f32x2 helpers ----------------
__device__ __forceinline__ u64 pack2(float x, float y) {
    u64 r; asm("mov.b64 %0,{%1,%2};" : "=l"(r) : "f"(x), "f"(y)); return r;
}
__device__ __forceinline__ float2 unpack2(u64 v) {
    float2 r; asm("mov.b64 {%0,%1},%2;" : "=f"(r.x), "=f"(r.y) : "l"(v)); return r;
}
__device__ __forceinline__ void ffma2(u64 &c, u64 a, u64 b) {
    asm("fma.rn.f32x2 %0,%1,%2,%0;" : "+l"(c) : "l"(a), "l"(b));
}

// ---------------- cp.async helpers (used by k_update only) ----------------
__device__ __forceinline__ uint32_t s_u32(const void* p) {
    uint32_t a;
    asm("{ .reg .u64 t; cvta.to.shared.u64 t, %1; cvt.u32.u64 %0, t; }" : "=r"(a) : "l"(p));
    return a;
}
__device__ __forceinline__ void cp16(uint32_t dst, const void* src, int src_bytes) {
    asm volatile("cp.async.cg.shared.global [%0], [%1], 16, %2;"
                 :: "r"(dst), "l"(src), "r"(src_bytes) : "memory");
}
#define CP_COMMIT() asm volatile("cp.async.commit_group;" ::: "memory")
#define CP_WAIT(n)  asm volatile("cp.async.wait_group %0;" :: "n"(n) : "memory")

// 8x8 per-thread micro-tile, K=32 step (proven). tx in [0,16), ty*8 rows.
__device__ __forceinline__ void mm_row(const float* __restrict__ A, int lda,
                                       int arow0, int kbase,
                                       const float* __restrict__ Bs,
                                       int tx, u64 acc[8][4]) {
#pragma unroll
    for (int kq = 0; kq < 8; ++kq) {
        int k0 = kq * 4;
        u64 bb[4][4];
#pragma unroll
        for (int kk = 0; kk < 4; ++kk) {
            const float* br = &Bs[(k0 + kk) * 128 + tx * 8];
            float4 b0 = *(const float4*)br;
            float4 b1 = *(const float4*)(br + 4);
            bb[kk][0] = pack2(b0.x, b0.y); bb[kk][1] = pack2(b0.z, b0.w);
            bb[kk][2] = pack2(b1.x, b1.y); bb[kk][3] = pack2(b1.z, b1.w);
        }
#pragma unroll
        for (int i = 0; i < 8; ++i) {
            float4 av = *(const float4*)&A[(arow0 + i) * lda + kbase + k0];
            float af[4] = { av.x, av.y, av.z, av.w };
#pragma unroll
            for (int kk = 0; kk < 4; ++kk) {
                u64 aa = pack2(af[kk], af[kk]);
#pragma unroll
                for (int jp = 0; jp < 4; ++jp) ffma2(acc[i][jp], aa, bb[kk][jp]);
            }
        }
    }
}

// fill Bs[32][128] from W rows [kb,kb+32) with 128 threads (float4)
__device__ __forceinline__ void fill_B(float* __restrict__ Bs,
                                       const float* __restrict__ W, int kb, int tid) {
    const float4* W4 = reinterpret_cast<const float4*>(W);
#pragma unroll
    for (int r = 0; r < 8; ++r) {
        int idx = r * 128 + tid;
        int kk = idx >> 5, j4 = idx & 31;
        *reinterpret_cast<float4*>(&Bs[kk * 128 + j4 * 4]) = W4[(size_t)(kb + kk) * 32 + j4];
    }
}
// 256-thread variant
__device__ __forceinline__ void fill_B256(float* __restrict__ Bs,
                                          const float* __restrict__ W, int kb, int tid) {
    const float4* W4 = reinterpret_cast<const float4*>(W);
#pragma unroll
    for (int r = 0; r < 4; ++r) {
        int idx = r * 256 + tid;
        int kk = idx >> 5, j4 = idx & 31;
        *reinterpret_cast<float4*>(&Bs[kk * 128 + j4 * 4]) = W4[(size_t)(kb + kk) * 32 + j4];
    }
}

// async fills (k_update)
__device__ __forceinline__ void cp_B(float* __restrict__ Bs,
                                     const float* __restrict__ W, int kb, int tid) {
    const float4* W4 = reinterpret_cast<const float4*>(W);
#pragma unroll
    for (int r = 0; r < 8; ++r) {
        int idx = r * 128 + tid;
        int kk = idx >> 5, j4 = idx & 31;
        cp16(s_u32(&Bs[kk * 128 + j4 * 4]), &W4[(size_t)(kb + kk) * 32 + j4], 16);
    }
}
__device__ __forceinline__ void cp_A(float* __restrict__ As,
                                     const float* __restrict__ src, int n0, int kb, int tid) {
#pragma unroll
    for (int r = 0; r < 4; ++r) {
        int idx = r * 128 + tid;
        int e = idx >> 3, c4 = idx & 7;
        int n = n0 + e;
        uint32_t dst = s_u32(&As[e * APAD + c4 * 4]);
        if (n < NN) cp16(dst, &src[(size_t)n * 128 + kb + c4 * 4], 16);
        else        cp16(dst, src, 0);
    }
}

// ---------------- merged count + fuse ----------------
__global__ void k_count_fuse(const int* __restrict__ ei,
                             const float* __restrict__ msg_w2,
                             const float* __restrict__ msg_b2,
                             const float* __restrict__ upd_w1) {
    if (blockIdx.x < CNT_BLKS) {
        int e = blockIdx.x * 256 + threadIdx.x;
        if (e < EE) atomicAdd(&g_cnt[ei[EE + e]], 1);
        return;
    }
    __shared__ float row[2][128];
    int fid = blockIdx.x - CNT_BLKS;
    int half = threadIdx.x >> 7;
    int c = threadIdx.x & 127;
    int r = fid * 2 + half;
    int l = r / 129, k = r % 129;
    row[half][c] = (k < 128) ? msg_w2[(size_t)l * 16384 + k * 128 + c]
                             : msg_b2[l * 128 + c];
    __syncthreads();
    const float* Wb = upd_w1 + (size_t)l * 32768 + 16384;
    float s = 0.f;
#pragma unroll 8
    for (int j = 0; j < 128; ++j) s += row[half][j] * Wb[j * 128 + c];
    if (k < 128) g_Wc[l][k * 128 + c] = s;
    else         g_bc[l][c] = s;
}

__global__ void k_scan() {
    __shared__ int ssum[256];
    int tid = threadIdx.x;
    int base = tid * 40;
    int s = 0;
    for (int i = 0; i < 40; ++i) {
        int n = base + i;
        if (n < NN) s += g_cnt[n];
    }
    ssum[tid] = s;
    __syncthreads();
    for (int o = 1; o < 256; o <<= 1) {
        int u = (tid >= o) ? ssum[tid - o] : 0;
        int v = ssum[tid];
        __syncthreads();
        ssum[tid] = u + v;
        __syncthreads();
    }
    int run = (tid > 0) ? ssum[tid - 1] : 0;
    for (int i = 0; i < 40; ++i) {
        int n = base + i;
        if (n < NN) {
            int c = g_cnt[n];
            g_off[n] = run;
            g_cur[n] = run;
            g_inv[n]  = 1.0f / fmaxf((float)c, 1.0f);
            g_flag[n] = (c > 0) ? 1.0f : 0.0f;
            run += c;
        }
    }
}

// ---------------- merged place + encoder ----------------
#define SM_ENC ((64 * TPAD + 32 * 128 + 384 + 768 + 128) * 4)
__global__ __launch_bounds__(128, 4) void k_place_enc(
    const int* __restrict__ ei, const float* __restrict__ ea,
    const float* __restrict__ x,
    const float* __restrict__ w1, const float* __restrict__ b1,
    const float* __restrict__ w2, const float* __restrict__ b2) {
    extern __shared__ float sm[];
    if (blockIdx.x < PLACE_BLKS) {
        int e = blockIdx.x * 128 + threadIdx.x;
        if (e < EE) {
            int tgt = ei[EE + e], src = ei[e];
            int pos = atomicAdd(&g_cur[tgt], 1);
            float4 r;
            r.x = __int_as_float(src);
            r.y = ea[(size_t)e * 3];
            r.z = ea[(size_t)e * 3 + 1];
            r.w = ea[(size_t)e * 3 + 2];
            g_rec[pos] = r;
        }
        return;
    }
    float* Ts  = sm;
    float* Bs  = Ts + 64 * TPAD;
    float* sx  = Bs + 32 * 128;
    float* sw1 = sx + 384;
    float* sb1 = sw1 + 768;
    int tid = threadIdx.x;
    int tx = tid & 15, ty = tid >> 4;
    int n0 = (blockIdx.x - PLACE_BLKS) * 64;

    sb1[tid] = b1[tid];
    for (int i = tid; i < 384; i += 128) {
        int n = n0 + i / 6;
        sx[i] = (n < NN) ? x[(size_t)n * 6 + (i % 6)] : 0.f;
    }
    for (int i = tid; i < 768; i += 128) sw1[i] = w1[i];
    __syncthreads();

#pragma unroll
    for (int i = 0; i < 8; ++i) {
        int e = ty * 8 + i;
        const float* xr = &sx[e * 6];
#pragma unroll
        for (int q = 0; q < 8; ++q) {
            int j = tx * 8 + q;
            float s = sb1[j];
#pragma unroll
            for (int k = 0; k < 6; ++k) s += xr[k] * sw1[k * 128 + j];
            Ts[e * TPAD + j] = fmaxf(s, 0.f);
        }
    }

    u64 acc[8][4];
#pragma unroll
    for (int i = 0; i < 8; ++i)
#pragma unroll
        for (int jp = 0; jp < 4; ++jp) acc[i][jp] = 0ull;
    for (int kt = 0; kt < 4; ++kt) {
        __syncthreads();
        fill_B(Bs, w2, kt * 32, tid);
        __syncthreads();
        mm_row(Ts, TPAD, ty * 8, kt * 32, Bs, tx, acc);
    }
    float bj[8];
#pragma unroll
    for (int q = 0; q < 8; ++q) bj[q] = b2[tx * 8 + q];
#pragma unroll
    for (int i = 0; i < 8; ++i) {
        int n = n0 + ty * 8 + i;
        if (n < NN) {
#pragma unroll
            for (int jp = 0; jp < 4; ++jp) {
                float2 c = unpack2(acc[i][jp]);
                c.x += bj[2 * jp]; c.y += bj[2 * jp + 1];
                *(float2*)&g_h[(size_t)n * 128 + tx * 8 + 2 * jp] = c;
            }
        }
    }
}

// ---------------- P/Q: grid (NB64, 2), M=64 / 128 thr, sync fill (round-11 champion) ----------------
#define SM_G ((64 * APAD + 32 * 128) * 4)
__global__ __launch_bounds__(128, 4) void k_pq(const float* __restrict__ W1,
                                               const float* __restrict__ B1m) {
    extern __shared__ float sm[];
    float* As = sm;
    float* Bs = sm + 64 * APAD;
    int tid = threadIdx.x;
    int tx = tid & 15, ty = tid >> 4;
    int n0 = blockIdx.x * 64;
    int sel = blockIdx.y;
    const float* W = (sel == 0) ? W1 : (W1 + 128 * 128);
    float* outp = (sel == 0) ? g_P : g_Q;

    u64 acc[8][4];
#pragma unroll
    for (int i = 0; i < 8; ++i)
#pragma unroll
        for (int jp = 0; jp < 4; ++jp) acc[i][jp] = 0ull;

    for (int kt = 0; kt < 4; ++kt) {
        int kb = kt * 32;
        __syncthreads();
#pragma unroll
        for (int r = 0; r < 4; ++r) {
            int idx = r * 128 + tid;
            int e = idx >> 3, c4 = idx & 7;
            int n = n0 + e;
            float4 v = make_float4(0.f, 0.f, 0.f, 0.f);
            if (n < NN) v = *(const float4*)&g_h[(size_t)n * 128 + kb + c4 * 4];
            *(float4*)&As[e * APAD + c4 * 4] = v;
        }
        fill_B(Bs, W, kb, tid);
        __syncthreads();
        mm_row(As, APAD, ty * 8, 0, Bs, tx, acc);
    }

    float bj[8];
#pragma unroll
    for (int q = 0; q < 8; ++q) bj[q] = (sel == 0) ? B1m[tx * 8 + q] : 0.f;
#pragma unroll
    for (int i = 0; i < 8; ++i) {
        int n = n0 + ty * 8 + i;
        if (n < NN) {
#pragma unroll
            for (int jp = 0; jp < 4; ++jp) {
                float2 c = unpack2(acc[i][jp]);
                c.x += bj[2 * jp]; c.y += bj[2 * jp + 1];
                *(float2*)&outp[(size_t)n * 128 + tx * 8 + 2 * jp] = c;
            }
        }
    }
}

// ---------------- merged edge reduction + U GEMM ----------------
// blocks [0, EDGE_BLKS): edge seg-reduce (8 warps/node). blocks >= : U = h@Wa, M=128/256thr.
__device__ __forceinline__ void edge_acc(float4& a, float4 P4, float4 q, float4 r,
                                         float4 wc0, float4 wc1, float4 wc2) {
    a.x += fmaxf(P4.x + q.x + r.y * wc0.x + r.z * wc1.x + r.w * wc2.x, 0.f);
    a.y += fmaxf(P4.y + q.y + r.y * wc0.y + r.z * wc1.y + r.w * wc2.y, 0.f);
    a.z += fmaxf(P4.z + q.z + r.y * wc0.z + r.z * wc1.z + r.w * wc2.z, 0.f);
    a.w += fmaxf(P4.w + q.w + r.y * wc0.w + r.z * wc1.w + r.w * wc2.w, 0.f);
}

#define SM_EU ((128 * APAD + 32 * 128) * 4)
__global__ __launch_bounds__(256, 2) void k_edge_u(const float* __restrict__ W1,
                                                   const float* __restrict__ Wa) {
    extern __shared__ float sm[];
    if (blockIdx.x < EDGE_BLKS) {
        int wid = threadIdx.x >> 5, lane = threadIdx.x & 31;
        int n = blockIdx.x * 8 + wid;
        if (n >= NN) return;
        int c4 = lane * 4;
        float4 P4  = *(const float4*)&g_P[(size_t)n * 128 + c4];
        float4 wc0 = *(const float4*)&W1[(size_t)256 * 128 + c4];
        float4 wc1 = *(const float4*)&W1[(size_t)257 * 128 + c4];
        float4 wc2 = *(const float4*)&W1[(size_t)258 * 128 + c4];
        int start = g_off[n], deg = g_cnt[n];
        float4 a0 = make_float4(0.f, 0.f, 0.f, 0.f);
        float4 a1 = make_float4(0.f, 0.f, 0.f, 0.f);
        int i = 0;
        for (; i + 3 < deg; i += 4) {
            float4 r0 = g_rec[start + i];
            float4 r1 = g_rec[start + i + 1];
            float4 r2 = g_rec[start + i + 2];
            float4 r3 = g_rec[start + i + 3];
            float4 q0 = *(const float4*)&g_Q[(size_t)__float_as_int(r0.x) * 128 + c4];
            float4 q1 = *(const float4*)&g_Q[(size_t)__float_as_int(r1.x) * 128 + c4];
            float4 q2 = *(const float4*)&g_Q[(size_t)__float_as_int(r2.x) * 128 + c4];
            float4 q3 = *(const float4*)&g_Q[(size_t)__float_as_int(r3.x) * 128 + c4];
            edge_acc(a0, P4, q0, r0, wc0, wc1, wc2);
            edge_acc(a1, P4, q1, r1, wc0, wc1, wc2);
            edge_acc(a0, P4, q2, r2, wc0, wc1, wc2);
            edge_acc(a1, P4, q3, r3, wc0, wc1, wc2);
        }
        for (; i < deg; ++i) {
            float4 r0 = g_rec[start + i];
            float4 q0 = *(const float4*)&g_Q[(size_t)__float_as_int(r0.x) * 128 + c4];
            edge_acc(a0, P4, q0, r0, wc0, wc1, wc2);
        }
        float iv = g_inv[n];
        *(float4*)&g_agg[(size_t)n * 128 + c4] =
            make_float4((a0.x + a1.x) * iv, (a0.y + a1.y) * iv,
                        (a0.z + a1.z) * iv, (a0.w + a1.w) * iv);
        return;
    }
    // U GEMM: M=128, 256 threads (round-8 proven shape)
    float* As = sm;                     // [128][APAD]
    float* Bs = sm + 128 * APAD;        // [32][128]
    int tid = threadIdx.x;
    int tx = tid & 15, ty = tid >> 4;   // ty 0..15
    int n0 = (blockIdx.x - EDGE_BLKS) * 128;

    u64 acc[8][4];
#pragma unroll
    for (int i = 0; i < 8; ++i)
#pragma unroll
        for (int jp = 0; jp < 4; ++jp) acc[i][jp] = 0ull;

    for (int kt = 0; kt < 4; ++kt) {
        int kb = kt * 32;
        __syncthreads();
#pragma unroll
        for (int r = 0; r < 4; ++r) {
            int idx = r * 256 + tid;          // 1024 float4 slots
            int e = idx >> 3, c4 = idx & 7;
            int n = n0 + e;
            float4 v = make_float4(0.f, 0.f, 0.f, 0.f);
            if (n < NN) v = *(const float4*)&g_h[(size_t)n * 128 + kb + c4 * 4];
            *(float4*)&As[e * APAD + c4 * 4] = v;
        }
        fill_B256(Bs, Wa, kb, tid);
        __syncthreads();
        mm_row(As, APAD, ty * 8, 0, Bs, tx, acc);
    }

#pragma unroll
    for (int i = 0; i < 8; ++i) {
        int n = n0 + ty * 8 + i;
        if (n < NN) {
#pragma unroll
            for (int jp = 0; jp < 4; ++jp) {
                float2 c = unpack2(acc[i][jp]);
                *(float2*)&g_U[(size_t)n * 128 + tx * 8 + 2 * jp] = c;
            }
        }
    }
}

// ---------------- update MLP: cp.async double-buffered (round-12 version, helped) ----------------
#define SM_UPD ((2 * 64 * APAD + 2 * 32 * 128 + 64 * TPAD) * 4)
__global__ __launch_bounds__(128, 2) void k_update(
    const float* __restrict__ B1, int layer,
    const float* __restrict__ W2, const float* __restrict__ B2,
    const float* __restrict__ lng, const float* __restrict__ lnb) {
    extern __shared__ float sm[];
    float* Asb[2] = { sm, sm + 64 * APAD };
    float* Bsb[2] = { sm + 2 * 64 * APAD, sm + 2 * 64 * APAD + 32 * 128 };
    float* Ts = sm + 2 * 64 * APAD + 2 * 32 * 128;
    __shared__ float s_flag[64];
    __shared__ float s_bc[128];

    int tid = threadIdx.x;
    int tx = tid & 15, ty = tid >> 4;
    int n0 = blockIdx.x * 64;
    const float* __restrict__ Wc = g_Wc[layer];

    if (tid < 64) {
        int n = n0 + tid;
        s_flag[tid] = (n < NN) ? g_flag[n] : 0.f;
    }
    s_bc[tid] = g_bc[layer][tid];

    u64 acc[8][4];
#pragma unroll
    for (int i = 0; i < 8; ++i)
#pragma unroll
        for (int jp = 0; jp < 4; ++jp) acc[i][jp] = 0ull;

    cp_A(Asb[0], g_agg, n0, 0, tid);
    cp_B(Bsb[0], Wc, 0, tid);
    CP_COMMIT();
#pragma unroll
    for (int kt = 0; kt < 4; ++kt) {
        if (kt < 3) {
            int nb = (kt + 1) & 1;
            cp_A(Asb[nb], g_agg, n0, (kt + 1) * 32, tid);
            cp_B(Bsb[nb], Wc, (kt + 1) * 32, tid);
            CP_COMMIT();
            CP_WAIT(1);
        } else {
            CP_WAIT(0);
        }
        __syncthreads();
        mm_row(Asb[kt & 1], APAD, ty * 8, 0, Bsb[kt & 1], tx, acc);
        __syncthreads();
    }

    {
        float bj[8], bc[8];
#pragma unroll
        for (int q = 0; q < 8; ++q) { bj[q] = B1[tx * 8 + q]; bc[q] = s_bc[tx * 8 + q]; }
#pragma unroll
        for (int i = 0; i < 8; ++i) {
            int e = ty * 8 + i;
            int n = n0 + e;
            float fz = s_flag[e];
#pragma unroll
            for (int jp = 0; jp < 4; ++jp) {
                float2 c = unpack2(acc[i][jp]);
                float u0 = 0.f, u1 = 0.f;
                if (n < NN) {
                    float2 uv = *(const float2*)&g_U[(size_t)n * 128 + tx * 8 + 2 * jp];
                    u0 = uv.x; u1 = uv.y;
                }
                c.x = fmaxf(c.x + u0 + bj[2 * jp]     + fz * bc[2 * jp],     0.f);
                c.y = fmaxf(c.y + u1 + bj[2 * jp + 1] + fz * bc[2 * jp + 1], 0.f);
                *(float2*)&Ts[e * TPAD + tx * 8 + 2 * jp] = c;
            }
        }
        __syncthreads();
    }

    u64 acc2[8][4];
#pragma unroll
    for (int i = 0; i < 8; ++i)
#pragma unroll
        for (int jp = 0; jp < 4; ++jp) acc2[i][jp] = 0ull;

    cp_B(Bsb[0], W2, 0, tid);
    CP_COMMIT();
#pragma unroll
    for (int kt = 0; kt < 4; ++kt) {
        if (kt < 3) {
            cp_B(Bsb[(kt + 1) & 1], W2, (kt + 1) * 32, tid);
            CP_COMMIT();
            CP_WAIT(1);
        } else {
            CP_WAIT(0);
        }
        __syncthreads();
        mm_row(Ts, TPAD, ty * 8, kt * 32, Bsb[kt & 1], tx, acc2);
        __syncthreads();
    }

    {
        float bj[8];
#pragma unroll
        for (int q = 0; q < 8; ++q) bj[q] = B2[tx * 8 + q];
#pragma unroll
        for (int i = 0; i < 8; ++i) {
            int e = ty * 8 + i;
            int n = n0 + e;
#pragma unroll
            for (int jp = 0; jp < 4; ++jp) {
                float2 c = unpack2(acc2[i][jp]);
                float h0 = 0.f, h1 = 0.f;
                if (n < NN) {
                    float2 hv = *(const float2*)&g_h[(size_t)n * 128 + tx * 8 + 2 * jp];
                    h0 = hv.x; h1 = hv.y;
                }
                c.x += bj[2 * jp] + h0;
                c.y += bj[2 * jp + 1] + h1;
                *(float2*)&Ts[e * TPAD + tx * 8 + 2 * jp] = c;
            }
        }
        __syncthreads();
    }

    {
        int wid = tid >> 5, lane = tid & 31;
        for (int rr = 0; rr < 16; ++rr) {
            int e = wid * 16 + rr;
            int n = n0 + e;
            float v0 = Ts[e * TPAD + lane];
            float v1 = Ts[e * TPAD + lane + 32];
            float v2 = Ts[e * TPAD + lane + 64];
            float v3 = Ts[e * TPAD + lane + 96];
            float s = v0 + v1 + v2 + v3;
#pragma unroll
            for (int o = 16; o > 0; o >>= 1) s += __shfl_xor_sync(0xffffffffu, s, o);
            float mu = s * (1.0f / 128.0f);
            float d0 = v0 - mu, d1 = v1 - mu, d2 = v2 - mu, d3 = v3 - mu;
            float q = d0 * d0 + d1 * d1 + d2 * d2 + d3 * d3;
#pragma unroll
            for (int o = 16; o > 0; o >>= 1) q += __shfl_xor_sync(0xffffffffu, q, o);
            float rs = rsqrtf(q * (1.0f / 128.0f) + 1e-5f);
            if (n < NN) {
                size_t base = (size_t)n * 128;
                g_h[base + lane]      = d0 * rs * lng[lane]      + lnb[lane];
                g_h[base + lane + 32] = d1 * rs * lng[lane + 32] + lnb[lane + 32];
                g_h[base + lane + 64] = d2 * rs * lng[lane + 64] + lnb[lane + 64];
                g_h[base + lane + 96] = d3 * rs * lng[lane + 96] + lnb[lane + 96];
            }
        }
    }
}

// ---------------- fused decoder, M=64 / 128 thr ----------------
#define SM_DEC ((64 * TPAD + 32 * 128 + 128) * 4)
__global__ __launch_bounds__(128, 4) void k_dec(
    const float* __restrict__ w1, const float* __restrict__ b1,
    const float* __restrict__ w2, const float* __restrict__ b2,
    float* __restrict__ out) {
    extern __shared__ float sm[];
    float* Ts  = sm;
    float* Bs  = Ts + 64 * TPAD;
    float* sw2 = Bs + 32 * 128;
    int tid = threadIdx.x;
    int tx = tid & 15, ty = tid >> 4;
    int wid = tid >> 5, lane = tid & 31;
    int n0 = blockIdx.x * 64;

    sw2[tid] = w2[tid];
#pragma unroll
    for (int r = 0; r < 16; ++r) {
        int idx = r * 128 + tid;
        int e = idx >> 5, j4 = idx & 31;
        int n = n0 + e;
        float4 v = make_float4(0.f, 0.f, 0.f, 0.f);
        if (n < NN) v = *(const float4*)&g_h[(size_t)n * 128 + j4 * 4];
        *(float4*)&Ts[e * TPAD + j4 * 4] = v;
    }
    __syncthreads();

    u64 acc[8][4];
#pragma unroll
    for (int i = 0; i < 8; ++i)
#pragma unroll
        for (int jp = 0; jp < 4; ++jp) acc[i][jp] = 0ull;
    for (int kt = 0; kt < 4; ++kt) {
        __syncthreads();
        fill_B(Bs, w1, kt * 32, tid);
        __syncthreads();
        mm_row(Ts, TPAD, ty * 8, kt * 32, Bs, tx, acc);
    }
    float tv[8][8];
    {
        float bj[8];
#pragma unroll
        for (int q = 0; q < 8; ++q) bj[q] = b1[tx * 8 + q];
#pragma unroll
        for (int i = 0; i < 8; ++i)
#pragma unroll
            for (int jp = 0; jp < 4; ++jp) {
                float2 c = unpack2(acc[i][jp]);
                tv[i][2 * jp]     = fmaxf(c.x + bj[2 * jp], 0.f);
                tv[i][2 * jp + 1] = fmaxf(c.y + bj[2 * jp + 1], 0.f);
            }
    }
    __syncthreads();
#pragma unroll
    for (int i = 0; i < 8; ++i) {
        int e = ty * 8 + i;
#pragma unroll
        for (int q = 0; q < 8; ++q) Ts[e * TPAD + tx * 8 + q] = tv[i][q];
    }
    __syncthreads();

    for (int rr = 0; rr < 16; ++rr) {
        int e = wid * 16 + rr;
        int n = n0 + e;
        float4 t = *(const float4*)&Ts[e * TPAD + lane * 4];
        float4 w = *(const float4*)&sw2[lane * 4];
        float s = t.x * w.x + t.y * w.y + t.z * w.z + t.w * w.w;
#pragma unroll
        for (int o = 16; o > 0; o >>= 1) s += __shfl_xor_sync(0xffffffffu, s, o);
        if (lane == 0 && n < NN) out[n] = s + b2[0];
    }
}

// ---------------- launch ----------------
extern "C" void kernel_launch(void* const* d_in, const int* in_sizes, int n_in,
                              void* d_out, int out_size) {
    const float* x      = (const float*)d_in[0];
    const int*   ei     = (const int*)  d_in[1];
    const float* eattr  = (const float*)d_in[2];
    const float* enc_w1 = (const float*)d_in[3];
    const float* enc_b1 = (const float*)d_in[4];
    const float* enc_w2 = (const float*)d_in[5];
    const float* enc_b2 = (const float*)d_in[6];
    const float* msg_w1 = (const float*)d_in[7];
    const float* msg_b1 = (const float*)d_in[8];
    const float* msg_w2 = (const float*)d_in[9];
    const float* msg_b2 = (const float*)d_in[10];
    const float* upd_w1 = (const float*)d_in[11];
    const float* upd_b1 = (const float*)d_in[12];
    const float* upd_w2 = (const float*)d_in[13];
    const float* upd_b2 = (const float*)d_in[14];
    const float* ln_g   = (const float*)d_in[15];
    const float* ln_b   = (const float*)d_in[16];
    const float* dec_w1 = (const float*)d_in[17];
    const float* dec_b1 = (const float*)d_in[18];
    const float* dec_w2 = (const float*)d_in[19];
    const float* dec_b2 = (const float*)d_in[20];
    float* out = (float*)d_out;

    cudaFuncSetAttribute(k_place_enc, cudaFuncAttributeMaxDynamicSharedMemorySize, SM_ENC);
    cudaFuncSetAttribute(k_pq,        cudaFuncAttributeMaxDynamicSharedMemorySize, SM_G);
    cudaFuncSetAttribute(k_edge_u,    cudaFuncAttributeMaxDynamicSharedMemorySize, SM_EU);
    cudaFuncSetAttribute(k_update,    cudaFuncAttributeMaxDynamicSharedMemorySize, SM_UPD);
    cudaFuncSetAttribute(k_dec,       cudaFuncAttributeMaxDynamicSharedMemorySize, SM_DEC);

    void* cntp = nullptr;
    cudaGetSymbolAddress(&cntp, g_cnt);
    cudaMemsetAsync(cntp, 0, NN * sizeof(int));
    k_count_fuse<<<CNT_BLKS + 258, 256>>>(ei, msg_w2, msg_b2, upd_w1);
    k_scan<<<1, 256>>>();
    k_place_enc<<<PLACE_BLKS + NB64, 128, SM_ENC>>>(ei, eattr, x,
                                                    enc_w1, enc_b1, enc_w2, enc_b2);

    for (int l = 0; l < 4; ++l) {
        const float* W1l = msg_w1 + (size_t)l * 259 * 128;
        k_pq<<<dim3(NB64, 2), 128, SM_G>>>(W1l, msg_b1 + (size_t)l * 128);
        k_edge_u<<<EDGE_BLKS + NB128, 256, SM_EU>>>(W1l, upd_w1 + (size_t)l * 256 * 128);
        k_update<<<NB64, 128, SM_UPD>>>(
            upd_b1 + (size_t)l * 128, l,
            upd_w2 + (size_t)l * 128 * 128, upd_b2 + (size_t)l * 128,
            ln_g + (size_t)l * 128, ln_b + (size_t)l * 128);
    }

    k_dec<<<NB64, 128, SM_DEC>>>(dec_w1, dec_b1, dec_w2, dec_b2, out);
}

// round 14
// speedup vs baseline: 1.1950x; 1.1950x over previous
#include <cuda_runtime.h>
#include <cstdint>

#define NN 10000
#define EE 400000
#define HH 128
#define TPAD 132
#define APAD 36
#define NB64 157   // ceil(NN/64)
#define CNT_BLKS 1563
#define PLACE_BLKS 3125

typedef unsigned long long u64;

// ---------------- device scratch ----------------
__device__ float g_h  [NN * HH];
__device__ float g_agg[NN * HH];   // Rmean
__device__ float g_P  [NN * HH];
__device__ float g_Q  [NN * HH];
__device__ float g_U  [NN * HH];   // h @ Wa_upd
__device__ float g_inv [NN];
__device__ float g_flag[NN];
__device__ int   g_cnt[NN];
__device__ int   g_off[NN];
__device__ int   g_cur[NN];
__device__ float4 g_rec[EE];
__device__ float g_Wc[4][HH * HH];
__device__ float g_bc[4][HH];

// ---------------- packed f32x2 helpers ----------------
__device__ __forceinline__ u64 pack2(float x, float y) {
    u64 r; asm("mov.b64 %0,{%1,%2};" : "=l"(r) : "f"(x), "f"(y)); return r;
}
__device__ __forceinline__ float2 unpack2(u64 v) {
    float2 r; asm("mov.b64 {%0,%1},%2;" : "=f"(r.x), "=f"(r.y) : "l"(v)); return r;
}
__device__ __forceinline__ void ffma2(u64 &c, u64 a, u64 b) {
    asm("fma.rn.f32x2 %0,%1,%2,%0;" : "+l"(c) : "l"(a), "l"(b));
}

// ---------------- cp.async helpers (k_update only — measured win there) ----------------
__device__ __forceinline__ uint32_t s_u32(const void* p) {
    uint32_t a;
    asm("{ .reg .u64 t; cvta.to.shared.u64 t, %1; cvt.u32.u64 %0, t; }" : "=r"(a) : "l"(p));
    return a;
}
__device__ __forceinline__ void cp16(uint32_t dst, const void* src, int src_bytes) {
    asm volatile("cp.async.cg.shared.global [%0], [%1], 16, %2;"
                 :: "r"(dst), "l"(src), "r"(src_bytes) : "memory");
}
#define CP_COMMIT() asm volatile("cp.async.commit_group;" ::: "memory")
#define CP_WAIT(n)  asm volatile("cp.async.wait_group %0;" :: "n"(n) : "memory")

// 8x8 per-thread micro-tile, K=32 step (proven).
__device__ __forceinline__ void mm_row(const float* __restrict__ A, int lda,
                                       int arow0, int kbase,
                                       const float* __restrict__ Bs,
                                       int tx, u64 acc[8][4]) {
#pragma unroll
    for (int kq = 0; kq < 8; ++kq) {
        int k0 = kq * 4;
        u64 bb[4][4];
#pragma unroll
        for (int kk = 0; kk < 4; ++kk) {
            const float* br = &Bs[(k0 + kk) * 128 + tx * 8];
            float4 b0 = *(const float4*)br;
            float4 b1 = *(const float4*)(br + 4);
            bb[kk][0] = pack2(b0.x, b0.y); bb[kk][1] = pack2(b0.z, b0.w);
            bb[kk][2] = pack2(b1.x, b1.y); bb[kk][3] = pack2(b1.z, b1.w);
        }
#pragma unroll
        for (int i = 0; i < 8; ++i) {
            float4 av = *(const float4*)&A[(arow0 + i) * lda + kbase + k0];
            float af[4] = { av.x, av.y, av.z, av.w };
#pragma unroll
            for (int kk = 0; kk < 4; ++kk) {
                u64 aa = pack2(af[kk], af[kk]);
#pragma unroll
                for (int jp = 0; jp < 4; ++jp) ffma2(acc[i][jp], aa, bb[kk][jp]);
            }
        }
    }
}

// fill Bs[32][128] from W rows [kb,kb+32) with 128 threads (float4)
__device__ __forceinline__ void fill_B(float* __restrict__ Bs,
                                       const float* __restrict__ W, int kb, int tid) {
    const float4* W4 = reinterpret_cast<const float4*>(W);
#pragma unroll
    for (int r = 0; r < 8; ++r) {
        int idx = r * 128 + tid;
        int kk = idx >> 5, j4 = idx & 31;
        *reinterpret_cast<float4*>(&Bs[kk * 128 + j4 * 4]) = W4[(size_t)(kb + kk) * 32 + j4];
    }
}

// async fills (k_update)
__device__ __forceinline__ void cp_B(float* __restrict__ Bs,
                                     const float* __restrict__ W, int kb, int tid) {
    const float4* W4 = reinterpret_cast<const float4*>(W);
#pragma unroll
    for (int r = 0; r < 8; ++r) {
        int idx = r * 128 + tid;
        int kk = idx >> 5, j4 = idx & 31;
        cp16(s_u32(&Bs[kk * 128 + j4 * 4]), &W4[(size_t)(kb + kk) * 32 + j4], 16);
    }
}
__device__ __forceinline__ void cp_A(float* __restrict__ As,
                                     const float* __restrict__ src, int n0, int kb, int tid) {
#pragma unroll
    for (int r = 0; r < 4; ++r) {
        int idx = r * 128 + tid;
        int e = idx >> 3, c4 = idx & 7;
        int n = n0 + e;
        uint32_t dst = s_u32(&As[e * APAD + c4 * 4]);
        if (n < NN) cp16(dst, &src[(size_t)n * 128 + kb + c4 * 4], 16);
        else        cp16(dst, src, 0);
    }
}

// ---------------- merged count + fuse ----------------
__global__ void k_count_fuse(const int* __restrict__ ei,
                             const float* __restrict__ msg_w2,
                             const float* __restrict__ msg_b2,
                             const float* __restrict__ upd_w1) {
    if (blockIdx.x < CNT_BLKS) {
        int e = blockIdx.x * 256 + threadIdx.x;
        if (e < EE) atomicAdd(&g_cnt[ei[EE + e]], 1);
        return;
    }
    __shared__ float row[2][128];
    int fid = blockIdx.x - CNT_BLKS;
    int half = threadIdx.x >> 7;
    int c = threadIdx.x & 127;
    int r = fid * 2 + half;
    int l = r / 129, k = r % 129;
    row[half][c] = (k < 128) ? msg_w2[(size_t)l * 16384 + k * 128 + c]
                             : msg_b2[l * 128 + c];
    __syncthreads();
    const float* Wb = upd_w1 + (size_t)l * 32768 + 16384;
    float s = 0.f;
#pragma unroll 8
    for (int j = 0; j < 128; ++j) s += row[half][j] * Wb[j * 128 + c];
    if (k < 128) g_Wc[l][k * 128 + c] = s;
    else         g_bc[l][c] = s;
}

__global__ void k_scan() {
    __shared__ int ssum[256];
    int tid = threadIdx.x;
    int base = tid * 40;
    int s = 0;
    for (int i = 0; i < 40; ++i) {
        int n = base + i;
        if (n < NN) s += g_cnt[n];
    }
    ssum[tid] = s;
    __syncthreads();
    for (int o = 1; o < 256; o <<= 1) {
        int u = (tid >= o) ? ssum[tid - o] : 0;
        int v = ssum[tid];
        __syncthreads();
        ssum[tid] = u + v;
        __syncthreads();
    }
    int run = (tid > 0) ? ssum[tid - 1] : 0;
    for (int i = 0; i < 40; ++i) {
        int n = base + i;
        if (n < NN) {
            int c = g_cnt[n];
            g_off[n] = run;
            g_cur[n] = run;
            g_inv[n]  = 1.0f / fmaxf((float)c, 1.0f);
            g_flag[n] = (c > 0) ? 1.0f : 0.0f;
            run += c;
        }
    }
}

// ---------------- merged place + encoder ----------------
#define SM_ENC ((64 * TPAD + 32 * 128 + 384 + 768 + 128) * 4)
__global__ __launch_bounds__(128, 4) void k_place_enc(
    const int* __restrict__ ei, const float* __restrict__ ea,
    const float* __restrict__ x,
    const float* __restrict__ w1, const float* __restrict__ b1,
    const float* __restrict__ w2, const float* __restrict__ b2) {
    extern __shared__ float sm[];
    if (blockIdx.x < PLACE_BLKS) {
        int e = blockIdx.x * 128 + threadIdx.x;
        if (e < EE) {
            int tgt = ei[EE + e], src = ei[e];
            int pos = atomicAdd(&g_cur[tgt], 1);
            float4 r;
            r.x = __int_as_float(src);
            r.y = ea[(size_t)e * 3];
            r.z = ea[(size_t)e * 3 + 1];
            r.w = ea[(size_t)e * 3 + 2];
            g_rec[pos] = r;
        }
        return;
    }
    float* Ts  = sm;
    float* Bs  = Ts + 64 * TPAD;
    float* sx  = Bs + 32 * 128;
    float* sw1 = sx + 384;
    float* sb1 = sw1 + 768;
    int tid = threadIdx.x;
    int tx = tid & 15, ty = tid >> 4;
    int n0 = (blockIdx.x - PLACE_BLKS) * 64;

    sb1[tid] = b1[tid];
    for (int i = tid; i < 384; i += 128) {
        int n = n0 + i / 6;
        sx[i] = (n < NN) ? x[(size_t)n * 6 + (i % 6)] : 0.f;
    }
    for (int i = tid; i < 768; i += 128) sw1[i] = w1[i];
    __syncthreads();

#pragma unroll
    for (int i = 0; i < 8; ++i) {
        int e = ty * 8 + i;
        const float* xr = &sx[e * 6];
#pragma unroll
        for (int q = 0; q < 8; ++q) {
            int j = tx * 8 + q;
            float s = sb1[j];
#pragma unroll
            for (int k = 0; k < 6; ++k) s += xr[k] * sw1[k * 128 + j];
            Ts[e * TPAD + j] = fmaxf(s, 0.f);
        }
    }

    u64 acc[8][4];
#pragma unroll
    for (int i = 0; i < 8; ++i)
#pragma unroll
        for (int jp = 0; jp < 4; ++jp) acc[i][jp] = 0ull;
    for (int kt = 0; kt < 4; ++kt) {
        __syncthreads();
        fill_B(Bs, w2, kt * 32, tid);
        __syncthreads();
        mm_row(Ts, TPAD, ty * 8, kt * 32, Bs, tx, acc);
    }
    float bj[8];
#pragma unroll
    for (int q = 0; q < 8; ++q) bj[q] = b2[tx * 8 + q];
#pragma unroll
    for (int i = 0; i < 8; ++i) {
        int n = n0 + ty * 8 + i;
        if (n < NN) {
#pragma unroll
            for (int jp = 0; jp < 4; ++jp) {
                float2 c = unpack2(acc[i][jp]);
                c.x += bj[2 * jp]; c.y += bj[2 * jp + 1];
                *(float2*)&g_h[(size_t)n * 128 + tx * 8 + 2 * jp] = c;
            }
        }
    }
}

// ---------------- P/Q/U: grid (NB64, 3), M=64 / 128 thr, SYNC fill (measured best) ----------------
#define SM_G ((64 * APAD + 32 * 128) * 4)
__global__ __launch_bounds__(128, 4) void k_pqu(const float* __restrict__ W1,
                                                const float* __restrict__ B1m,
                                                const float* __restrict__ Wa) {
    extern __shared__ float sm[];
    float* As = sm;
    float* Bs = sm + 64 * APAD;
    int tid = threadIdx.x;
    int tx = tid & 15, ty = tid >> 4;
    int n0 = blockIdx.x * 64;
    int sel = blockIdx.y;
    const float* W = (sel == 0) ? W1 : (sel == 1) ? (W1 + 128 * 128) : Wa;
    float* outp = (sel == 0) ? g_P : (sel == 1) ? g_Q : g_U;

    u64 acc[8][4];
#pragma unroll
    for (int i = 0; i < 8; ++i)
#pragma unroll
        for (int jp = 0; jp < 4; ++jp) acc[i][jp] = 0ull;

    for (int kt = 0; kt < 4; ++kt) {
        int kb = kt * 32;
        __syncthreads();
#pragma unroll
        for (int r = 0; r < 4; ++r) {
            int idx = r * 128 + tid;
            int e = idx >> 3, c4 = idx & 7;
            int n = n0 + e;
            float4 v = make_float4(0.f, 0.f, 0.f, 0.f);
            if (n < NN) v = *(const float4*)&g_h[(size_t)n * 128 + kb + c4 * 4];
            *(float4*)&As[e * APAD + c4 * 4] = v;
        }
        fill_B(Bs, W, kb, tid);
        __syncthreads();
        mm_row(As, APAD, ty * 8, 0, Bs, tx, acc);
    }

    float bj[8];
#pragma unroll
    for (int q = 0; q < 8; ++q) bj[q] = (sel == 0) ? B1m[tx * 8 + q] : 0.f;
#pragma unroll
    for (int i = 0; i < 8; ++i) {
        int n = n0 + ty * 8 + i;
        if (n < NN) {
#pragma unroll
            for (int jp = 0; jp < 4; ++jp) {
                float2 c = unpack2(acc[i][jp]);
                c.x += bj[2 * jp]; c.y += bj[2 * jp + 1];
                *(float2*)&outp[(size_t)n * 128 + tx * 8 + 2 * jp] = c;
            }
        }
    }
}

// ---------------- segmented edge reduction: standalone, zero smem, 4-way unroll ----------------
__device__ __forceinline__ void edge_acc(float4& a, float4 P4, float4 q, float4 r,
                                         float4 wc0, float4 wc1, float4 wc2) {
    a.x += fmaxf(P4.x + q.x + r.y * wc0.x + r.z * wc1.x + r.w * wc2.x, 0.f);
    a.y += fmaxf(P4.y + q.y + r.y * wc0.y + r.z * wc1.y + r.w * wc2.y, 0.f);
    a.z += fmaxf(P4.z + q.z + r.y * wc0.z + r.z * wc1.z + r.w * wc2.z, 0.f);
    a.w += fmaxf(P4.w + q.w + r.y * wc0.w + r.z * wc1.w + r.w * wc2.w, 0.f);
}

__global__ void k_edge_seg(const float* __restrict__ W1) {
    int wid = threadIdx.x >> 5, lane = threadIdx.x & 31;
    int n = blockIdx.x * 8 + wid;
    if (n >= NN) return;
    int c4 = lane * 4;
    float4 P4  = *(const float4*)&g_P[(size_t)n * 128 + c4];
    float4 wc0 = *(const float4*)&W1[(size_t)256 * 128 + c4];
    float4 wc1 = *(const float4*)&W1[(size_t)257 * 128 + c4];
    float4 wc2 = *(const float4*)&W1[(size_t)258 * 128 + c4];
    int start = g_off[n], deg = g_cnt[n];
    float4 a0 = make_float4(0.f, 0.f, 0.f, 0.f);
    float4 a1 = make_float4(0.f, 0.f, 0.f, 0.f);
    int i = 0;
    for (; i + 3 < deg; i += 4) {
        float4 r0 = g_rec[start + i];
        float4 r1 = g_rec[start + i + 1];
        float4 r2 = g_rec[start + i + 2];
        float4 r3 = g_rec[start + i + 3];
        float4 q0 = *(const float4*)&g_Q[(size_t)__float_as_int(r0.x) * 128 + c4];
        float4 q1 = *(const float4*)&g_Q[(size_t)__float_as_int(r1.x) * 128 + c4];
        float4 q2 = *(const float4*)&g_Q[(size_t)__float_as_int(r2.x) * 128 + c4];
        float4 q3 = *(const float4*)&g_Q[(size_t)__float_as_int(r3.x) * 128 + c4];
        edge_acc(a0, P4, q0, r0, wc0, wc1, wc2);
        edge_acc(a1, P4, q1, r1, wc0, wc1, wc2);
        edge_acc(a0, P4, q2, r2, wc0, wc1, wc2);
        edge_acc(a1, P4, q3, r3, wc0, wc1, wc2);
    }
    for (; i < deg; ++i) {
        float4 r0 = g_rec[start + i];
        float4 q0 = *(const float4*)&g_Q[(size_t)__float_as_int(r0.x) * 128 + c4];
        edge_acc(a0, P4, q0, r0, wc0, wc1, wc2);
    }
    float iv = g_inv[n];
    *(float4*)&g_agg[(size_t)n * 128 + c4] =
        make_float4((a0.x + a1.x) * iv, (a0.y + a1.y) * iv,
                    (a0.z + a1.z) * iv, (a0.w + a1.w) * iv);
}

// ---------------- update MLP: cp.async double-buffered (measured best) ----------------
#define SM_UPD ((2 * 64 * APAD + 2 * 32 * 128 + 64 * TPAD) * 4)
__global__ __launch_bounds__(128, 2) void k_update(
    const float* __restrict__ B1, int layer,
    const float* __restrict__ W2, const float* __restrict__ B2,
    const float* __restrict__ lng, const float* __restrict__ lnb) {
    extern __shared__ float sm[];
    float* Asb[2] = { sm, sm + 64 * APAD };
    float* Bsb[2] = { sm + 2 * 64 * APAD, sm + 2 * 64 * APAD + 32 * 128 };
    float* Ts = sm + 2 * 64 * APAD + 2 * 32 * 128;
    __shared__ float s_flag[64];
    __shared__ float s_bc[128];

    int tid = threadIdx.x;
    int tx = tid & 15, ty = tid >> 4;
    int n0 = blockIdx.x * 64;
    const float* __restrict__ Wc = g_Wc[layer];

    if (tid < 64) {
        int n = n0 + tid;
        s_flag[tid] = (n < NN) ? g_flag[n] : 0.f;
    }
    s_bc[tid] = g_bc[layer][tid];

    u64 acc[8][4];
#pragma unroll
    for (int i = 0; i < 8; ++i)
#pragma unroll
        for (int jp = 0; jp < 4; ++jp) acc[i][jp] = 0ull;

    cp_A(Asb[0], g_agg, n0, 0, tid);
    cp_B(Bsb[0], Wc, 0, tid);
    CP_COMMIT();
#pragma unroll
    for (int kt = 0; kt < 4; ++kt) {
        if (kt < 3) {
            int nb = (kt + 1) & 1;
            cp_A(Asb[nb], g_agg, n0, (kt + 1) * 32, tid);
            cp_B(Bsb[nb], Wc, (kt + 1) * 32, tid);
            CP_COMMIT();
            CP_WAIT(1);
        } else {
            CP_WAIT(0);
        }
        __syncthreads();
        mm_row(Asb[kt & 1], APAD, ty * 8, 0, Bsb[kt & 1], tx, acc);
        __syncthreads();
    }

    {
        float bj[8], bc[8];
#pragma unroll
        for (int q = 0; q < 8; ++q) { bj[q] = B1[tx * 8 + q]; bc[q] = s_bc[tx * 8 + q]; }
#pragma unroll
        for (int i = 0; i < 8; ++i) {
            int e = ty * 8 + i;
            int n = n0 + e;
            float fz = s_flag[e];
#pragma unroll
            for (int jp = 0; jp < 4; ++jp) {
                float2 c = unpack2(acc[i][jp]);
                float u0 = 0.f, u1 = 0.f;
                if (n < NN) {
                    float2 uv = *(const float2*)&g_U[(size_t)n * 128 + tx * 8 + 2 * jp];
                    u0 = uv.x; u1 = uv.y;
                }
                c.x = fmaxf(c.x + u0 + bj[2 * jp]     + fz * bc[2 * jp],     0.f);
                c.y = fmaxf(c.y + u1 + bj[2 * jp + 1] + fz * bc[2 * jp + 1], 0.f);
                *(float2*)&Ts[e * TPAD + tx * 8 + 2 * jp] = c;
            }
        }
        __syncthreads();
    }

    u64 acc2[8][4];
#pragma unroll
    for (int i = 0; i < 8; ++i)
#pragma unroll
        for (int jp = 0; jp < 4; ++jp) acc2[i][jp] = 0ull;

    cp_B(Bsb[0], W2, 0, tid);
    CP_COMMIT();
#pragma unroll
    for (int kt = 0; kt < 4; ++kt) {
        if (kt < 3) {
            cp_B(Bsb[(kt + 1) & 1], W2, (kt + 1) * 32, tid);
            CP_COMMIT();
            CP_WAIT(1);
        } else {
            CP_WAIT(0);
        }
        __syncthreads();
        mm_row(Ts, TPAD, ty * 8, kt * 32, Bsb[kt & 1], tx, acc2);
        __syncthreads();
    }

    {
        float bj[8];
#pragma unroll
        for (int q = 0; q < 8; ++q) bj[q] = B2[tx * 8 + q];
#pragma unroll
        for (int i = 0; i < 8; ++i) {
            int e = ty * 8 + i;
            int n = n0 + e;
#pragma unroll
            for (int jp = 0; jp < 4; ++jp) {
                float2 c = unpack2(acc2[i][jp]);
                float h0 = 0.f, h1 = 0.f;
                if (n < NN) {
                    float2 hv = *(const float2*)&g_h[(size_t)n * 128 + tx * 8 + 2 * jp];
                    h0 = hv.x; h1 = hv.y;
                }
                c.x += bj[2 * jp] + h0;
                c.y += bj[2 * jp + 1] + h1;
                *(float2*)&Ts[e * TPAD + tx * 8 + 2 * jp] = c;
            }
        }
        __syncthreads();
    }

    {
        int wid = tid >> 5, lane = tid & 31;
        for (int rr = 0; rr < 16; ++rr) {
            int e = wid * 16 + rr;
            int n = n0 + e;
            float v0 = Ts[e * TPAD + lane];
            float v1 = Ts[e * TPAD + lane + 32];
            float v2 = Ts[e * TPAD + lane + 64];
            float v3 = Ts[e * TPAD + lane + 96];
            float s = v0 + v1 + v2 + v3;
#pragma unroll
            for (int o = 16; o > 0; o >>= 1) s += __shfl_xor_sync(0xffffffffu, s, o);
            float mu = s * (1.0f / 128.0f);
            float d0 = v0 - mu, d1 = v1 - mu, d2 = v2 - mu, d3 = v3 - mu;
            float q = d0 * d0 + d1 * d1 + d2 * d2 + d3 * d3;
#pragma unroll
            for (int o = 16; o > 0; o >>= 1) q += __shfl_xor_sync(0xffffffffu, q, o);
            float rs = rsqrtf(q * (1.0f / 128.0f) + 1e-5f);
            if (n < NN) {
                size_t base = (size_t)n * 128;
                g_h[base + lane]      = d0 * rs * lng[lane]      + lnb[lane];
                g_h[base + lane + 32] = d1 * rs * lng[lane + 32] + lnb[lane + 32];
                g_h[base + lane + 64] = d2 * rs * lng[lane + 64] + lnb[lane + 64];
                g_h[base + lane + 96] = d3 * rs * lng[lane + 96] + lnb[lane + 96];
            }
        }
    }
}

// ---------------- fused decoder, M=64 / 128 thr ----------------
#define SM_DEC ((64 * TPAD + 32 * 128 + 128) * 4)
__global__ __launch_bounds__(128, 4) void k_dec(
    const float* __restrict__ w1, const float* __restrict__ b1,
    const float* __restrict__ w2, const float* __restrict__ b2,
    float* __restrict__ out) {
    extern __shared__ float sm[];
    float* Ts  = sm;
    float* Bs  = Ts + 64 * TPAD;
    float* sw2 = Bs + 32 * 128;
    int tid = threadIdx.x;
    int tx = tid & 15, ty = tid >> 4;
    int wid = tid >> 5, lane = tid & 31;
    int n0 = blockIdx.x * 64;

    sw2[tid] = w2[tid];
#pragma unroll
    for (int r = 0; r < 16; ++r) {
        int idx = r * 128 + tid;
        int e = idx >> 5, j4 = idx & 31;
        int n = n0 + e;
        float4 v = make_float4(0.f, 0.f, 0.f, 0.f);
        if (n < NN) v = *(const float4*)&g_h[(size_t)n * 128 + j4 * 4];
        *(float4*)&Ts[e * TPAD + j4 * 4] = v;
    }
    __syncthreads();

    u64 acc[8][4];
#pragma unroll
    for (int i = 0; i < 8; ++i)
#pragma unroll
        for (int jp = 0; jp < 4; ++jp) acc[i][jp] = 0ull;
    for (int kt = 0; kt < 4; ++kt) {
        __syncthreads();
        fill_B(Bs, w1, kt * 32, tid);
        __syncthreads();
        mm_row(Ts, TPAD, ty * 8, kt * 32, Bs, tx, acc);
    }
    float tv[8][8];
    {
        float bj[8];
#pragma unroll
        for (int q = 0; q < 8; ++q) bj[q] = b1[tx * 8 + q];
#pragma unroll
        for (int i = 0; i < 8; ++i)
#pragma unroll
            for (int jp = 0; jp < 4; ++jp) {
                float2 c = unpack2(acc[i][jp]);
                tv[i][2 * jp]     = fmaxf(c.x + bj[2 * jp], 0.f);
                tv[i][2 * jp + 1] = fmaxf(c.y + bj[2 * jp + 1], 0.f);
            }
    }
    __syncthreads();
#pragma unroll
    for (int i = 0; i < 8; ++i) {
        int e = ty * 8 + i;
#pragma unroll
        for (int q = 0; q < 8; ++q) Ts[e * TPAD + tx * 8 + q] = tv[i][q];
    }
    __syncthreads();

    for (int rr = 0; rr < 16; ++rr) {
        int e = wid * 16 + rr;
        int n = n0 + e;
        float4 t = *(const float4*)&Ts[e * TPAD + lane * 4];
        float4 w = *(const float4*)&sw2[lane * 4];
        float s = t.x * w.x + t.y * w.y + t.z * w.z + t.w * w.w;
#pragma unroll
        for (int o = 16; o > 0; o >>= 1) s += __shfl_xor_sync(0xffffffffu, s, o);
        if (lane == 0 && n < NN) out[n] = s + b2[0];
    }
}

// ---------------- launch ----------------
extern "C" void kernel_launch(void* const* d_in, const int* in_sizes, int n_in,
                              void* d_out, int out_size) {
    const float* x      = (const float*)d_in[0];
    const int*   ei     = (const int*)  d_in[1];
    const float* eattr  = (const float*)d_in[2];
    const float* enc_w1 = (const float*)d_in[3];
    const float* enc_b1 = (const float*)d_in[4];
    const float* enc_w2 = (const float*)d_in[5];
    const float* enc_b2 = (const float*)d_in[6];
    const float* msg_w1 = (const float*)d_in[7];
    const float* msg_b1 = (const float*)d_in[8];
    const float* msg_w2 = (const float*)d_in[9];
    const float* msg_b2 = (const float*)d_in[10];
    const float* upd_w1 = (const float*)d_in[11];
    const float* upd_b1 = (const float*)d_in[12];
    const float* upd_w2 = (const float*)d_in[13];
    const float* upd_b2 = (const float*)d_in[14];
    const float* ln_g   = (const float*)d_in[15];
    const float* ln_b   = (const float*)d_in[16];
    const float* dec_w1 = (const float*)d_in[17];
    const float* dec_b1 = (const float*)d_in[18];
    const float* dec_w2 = (const float*)d_in[19];
    const float* dec_b2 = (const float*)d_in[20];
    float* out = (float*)d_out;

    cudaFuncSetAttribute(k_place_enc, cudaFuncAttributeMaxDynamicSharedMemorySize, SM_ENC);
    cudaFuncSetAttribute(k_pqu,       cudaFuncAttributeMaxDynamicSharedMemorySize, SM_G);
    cudaFuncSetAttribute(k_update,    cudaFuncAttributeMaxDynamicSharedMemorySize, SM_UPD);
    cudaFuncSetAttribute(k_dec,       cudaFuncAttributeMaxDynamicSharedMemorySize, SM_DEC);

    // degree count + Wc/bc precompute (one launch)
    void* cntp = nullptr;
    cudaGetSymbolAddress(&cntp, g_cnt);
    cudaMemsetAsync(cntp, 0, NN * sizeof(int));
    k_count_fuse<<<CNT_BLKS + 258, 256>>>(ei, msg_w2, msg_b2, upd_w1);
    k_scan<<<1, 256>>>();
    // record placement + encoder (one launch)
    k_place_enc<<<PLACE_BLKS + NB64, 128, SM_ENC>>>(ei, eattr, x,
                                                    enc_w1, enc_b1, enc_w2, enc_b2);

    for (int l = 0; l < 4; ++l) {
        const float* W1l = msg_w1 + (size_t)l * 259 * 128;
        k_pqu<<<dim3(NB64, 3), 128, SM_G>>>(W1l, msg_b1 + (size_t)l * 128,
                                            upd_w1 + (size_t)l * 256 * 128);
        k_edge_seg<<<NN / 8, 256>>>(W1l);
        k_update<<<NB64, 128, SM_UPD>>>(
            upd_b1 + (size_t)l * 128, l,
            upd_w2 + (size_t)l * 128 * 128, upd_b2 + (size_t)l * 128,
            ln_g + (size_t)l * 128, ln_b + (size_t)l * 128);
    }

    k_dec<<<NB64, 128, SM_DEC>>>(dec_w1, dec_b1, dec_w2, dec_b2, out);
}

// round 15
// speedup vs baseline: 1.2131x; 1.0151x over previous
#include <cuda_runtime.h>
#include <cstdint>

#define NN 10000
#define EE 400000
#define HH 128
#define TPAD 132
#define APAD 36
#define NB64 157   // ceil(NN/64)
#define CNT_BLKS 1563
#define PLACE_BLKS 3125

typedef unsigned long long u64;

// ---------------- device scratch ----------------
__device__ float g_h  [NN * HH];
__device__ float g_agg[NN * HH];   // Rmean
__device__ float g_P  [NN * HH];
__device__ float g_Q  [NN * HH];
__device__ float g_U  [NN * HH];   // h @ Wa_upd
__device__ float g_inv [NN];
__device__ float g_flag[NN];
__device__ int   g_cnt[NN];
__device__ int   g_off[NN];
__device__ int   g_cur[NN];
__device__ float4 g_rec[EE];
__device__ float g_Wc[4][HH * HH];
__device__ float g_bc[4][HH];

// ---------------- packed f32x2 helpers ----------------
__device__ __forceinline__ u64 pack2(float x, float y) {
    u64 r; asm("mov.b64 %0,{%1,%2};" : "=l"(r) : "f"(x), "f"(y)); return r;
}
__device__ __forceinline__ float2 unpack2(u64 v) {
    float2 r; asm("mov.b64 {%0,%1},%2;" : "=f"(r.x), "=f"(r.y) : "l"(v)); return r;
}
__device__ __forceinline__ void ffma2(u64 &c, u64 a, u64 b) {
    asm("fma.rn.f32x2 %0,%1,%2,%0;" : "+l"(c) : "l"(a), "l"(b));
}

// ---------------- cp.async helpers (k_update only) ----------------
__device__ __forceinline__ uint32_t s_u32(const void* p) {
    uint32_t a;
    asm("{ .reg .u64 t; cvta.to.shared.u64 t, %1; cvt.u32.u64 %0, t; }" : "=r"(a) : "l"(p));
    return a;
}
__device__ __forceinline__ void cp16(uint32_t dst, const void* src, int src_bytes) {
    asm volatile("cp.async.cg.shared.global [%0], [%1], 16, %2;"
                 :: "r"(dst), "l"(src), "r"(src_bytes) : "memory");
}
#define CP_COMMIT() asm volatile("cp.async.commit_group;" ::: "memory")
#define CP_WAIT(n)  asm volatile("cp.async.wait_group %0;" :: "n"(n) : "memory")

// 8x8 per-thread micro-tile, K=32 step (proven).
__device__ __forceinline__ void mm_row(const float* __restrict__ A, int lda,
                                       int arow0, int kbase,
                                       const float* __restrict__ Bs,
                                       int tx, u64 acc[8][4]) {
#pragma unroll
    for (int kq = 0; kq < 8; ++kq) {
        int k0 = kq * 4;
        u64 bb[4][4];
#pragma unroll
        for (int kk = 0; kk < 4; ++kk) {
            const float* br = &Bs[(k0 + kk) * 128 + tx * 8];
            float4 b0 = *(const float4*)br;
            float4 b1 = *(const float4*)(br + 4);
            bb[kk][0] = pack2(b0.x, b0.y); bb[kk][1] = pack2(b0.z, b0.w);
            bb[kk][2] = pack2(b1.x, b1.y); bb[kk][3] = pack2(b1.z, b1.w);
        }
#pragma unroll
        for (int i = 0; i < 8; ++i) {
            float4 av = *(const float4*)&A[(arow0 + i) * lda + kbase + k0];
            float af[4] = { av.x, av.y, av.z, av.w };
#pragma unroll
            for (int kk = 0; kk < 4; ++kk) {
                u64 aa = pack2(af[kk], af[kk]);
#pragma unroll
                for (int jp = 0; jp < 4; ++jp) ffma2(acc[i][jp], aa, bb[kk][jp]);
            }
        }
    }
}

// fill Bs[32][128] from W rows [kb,kb+32) with 128 threads (float4)
__device__ __forceinline__ void fill_B(float* __restrict__ Bs,
                                       const float* __restrict__ W, int kb, int tid) {
    const float4* W4 = reinterpret_cast<const float4*>(W);
#pragma unroll
    for (int r = 0; r < 8; ++r) {
        int idx = r * 128 + tid;
        int kk = idx >> 5, j4 = idx & 31;
        *reinterpret_cast<float4*>(&Bs[kk * 128 + j4 * 4]) = W4[(size_t)(kb + kk) * 32 + j4];
    }
}

// async fills (k_update)
__device__ __forceinline__ void cp_B(float* __restrict__ Bs,
                                     const float* __restrict__ W, int kb, int tid) {
    const float4* W4 = reinterpret_cast<const float4*>(W);
#pragma unroll
    for (int r = 0; r < 8; ++r) {
        int idx = r * 128 + tid;
        int kk = idx >> 5, j4 = idx & 31;
        cp16(s_u32(&Bs[kk * 128 + j4 * 4]), &W4[(size_t)(kb + kk) * 32 + j4], 16);
    }
}
__device__ __forceinline__ void cp_A(float* __restrict__ As,
                                     const float* __restrict__ src, int n0, int kb, int tid) {
#pragma unroll
    for (int r = 0; r < 4; ++r) {
        int idx = r * 128 + tid;
        int e = idx >> 3, c4 = idx & 7;
        int n = n0 + e;
        uint32_t dst = s_u32(&As[e * APAD + c4 * 4]);
        if (n < NN) cp16(dst, &src[(size_t)n * 128 + kb + c4 * 4], 16);
        else        cp16(dst, src, 0);
    }
}

// ---------------- merged count + fuse ----------------
__global__ void k_count_fuse(const int* __restrict__ ei,
                             const float* __restrict__ msg_w2,
                             const float* __restrict__ msg_b2,
                             const float* __restrict__ upd_w1) {
    if (blockIdx.x < CNT_BLKS) {
        int e = blockIdx.x * 256 + threadIdx.x;
        if (e < EE) atomicAdd(&g_cnt[ei[EE + e]], 1);
        return;
    }
    __shared__ float row[2][128];
    int fid = blockIdx.x - CNT_BLKS;
    int half = threadIdx.x >> 7;
    int c = threadIdx.x & 127;
    int r = fid * 2 + half;
    int l = r / 129, k = r % 129;
    row[half][c] = (k < 128) ? msg_w2[(size_t)l * 16384 + k * 128 + c]
                             : msg_b2[l * 128 + c];
    __syncthreads();
    const float* Wb = upd_w1 + (size_t)l * 32768 + 16384;
    float s = 0.f;
#pragma unroll 8
    for (int j = 0; j < 128; ++j) s += row[half][j] * Wb[j * 128 + c];
    if (k < 128) g_Wc[l][k * 128 + c] = s;
    else         g_bc[l][c] = s;
}

__global__ void k_scan() {
    __shared__ int ssum[256];
    int tid = threadIdx.x;
    int base = tid * 40;
    int s = 0;
    for (int i = 0; i < 40; ++i) {
        int n = base + i;
        if (n < NN) s += g_cnt[n];
    }
    ssum[tid] = s;
    __syncthreads();
    for (int o = 1; o < 256; o <<= 1) {
        int u = (tid >= o) ? ssum[tid - o] : 0;
        int v = ssum[tid];
        __syncthreads();
        ssum[tid] = u + v;
        __syncthreads();
    }
    int run = (tid > 0) ? ssum[tid - 1] : 0;
    for (int i = 0; i < 40; ++i) {
        int n = base + i;
        if (n < NN) {
            int c = g_cnt[n];
            g_off[n] = run;
            g_cur[n] = run;
            g_inv[n]  = 1.0f / fmaxf((float)c, 1.0f);
            g_flag[n] = (c > 0) ? 1.0f : 0.0f;
            run += c;
        }
    }
}

// ---------------- merged place + encoder ----------------
#define SM_ENC ((64 * TPAD + 32 * 128 + 384 + 768 + 128) * 4)
__global__ __launch_bounds__(128, 4) void k_place_enc(
    const int* __restrict__ ei, const float* __restrict__ ea,
    const float* __restrict__ x,
    const float* __restrict__ w1, const float* __restrict__ b1,
    const float* __restrict__ w2, const float* __restrict__ b2) {
    extern __shared__ float sm[];
    if (blockIdx.x < PLACE_BLKS) {
        int e = blockIdx.x * 128 + threadIdx.x;
        if (e < EE) {
            int tgt = ei[EE + e], src = ei[e];
            int pos = atomicAdd(&g_cur[tgt], 1);
            float4 r;
            r.x = __int_as_float(src);
            r.y = ea[(size_t)e * 3];
            r.z = ea[(size_t)e * 3 + 1];
            r.w = ea[(size_t)e * 3 + 2];
            g_rec[pos] = r;
        }
        return;
    }
    float* Ts  = sm;
    float* Bs  = Ts + 64 * TPAD;
    float* sx  = Bs + 32 * 128;
    float* sw1 = sx + 384;
    float* sb1 = sw1 + 768;
    int tid = threadIdx.x;
    int tx = tid & 15, ty = tid >> 4;
    int n0 = (blockIdx.x - PLACE_BLKS) * 64;

    sb1[tid] = b1[tid];
    for (int i = tid; i < 384; i += 128) {
        int n = n0 + i / 6;
        sx[i] = (n < NN) ? x[(size_t)n * 6 + (i % 6)] : 0.f;
    }
    for (int i = tid; i < 768; i += 128) sw1[i] = w1[i];
    __syncthreads();

#pragma unroll
    for (int i = 0; i < 8; ++i) {
        int e = ty * 8 + i;
        const float* xr = &sx[e * 6];
#pragma unroll
        for (int q = 0; q < 8; ++q) {
            int j = tx * 8 + q;
            float s = sb1[j];
#pragma unroll
            for (int k = 0; k < 6; ++k) s += xr[k] * sw1[k * 128 + j];
            Ts[e * TPAD + j] = fmaxf(s, 0.f);
        }
    }

    u64 acc[8][4];
#pragma unroll
    for (int i = 0; i < 8; ++i)
#pragma unroll
        for (int jp = 0; jp < 4; ++jp) acc[i][jp] = 0ull;
    for (int kt = 0; kt < 4; ++kt) {
        __syncthreads();
        fill_B(Bs, w2, kt * 32, tid);
        __syncthreads();
        mm_row(Ts, TPAD, ty * 8, kt * 32, Bs, tx, acc);
    }
    float bj[8];
#pragma unroll
    for (int q = 0; q < 8; ++q) bj[q] = b2[tx * 8 + q];
#pragma unroll
    for (int i = 0; i < 8; ++i) {
        int n = n0 + ty * 8 + i;
        if (n < NN) {
#pragma unroll
            for (int jp = 0; jp < 4; ++jp) {
                float2 c = unpack2(acc[i][jp]);
                c.x += bj[2 * jp]; c.y += bj[2 * jp + 1];
                *(float2*)&g_h[(size_t)n * 128 + tx * 8 + 2 * jp] = c;
            }
        }
    }
}

// ---------------- generic M=64/128thr GEMM body (used by k_pq and k_u) ----------------
#define SM_G ((64 * APAD + 32 * 128) * 4)
__device__ __forceinline__ void gemm64(const float* __restrict__ W,
                                       const float* __restrict__ bias,
                                       float* __restrict__ outp, int n0,
                                       float* sm, int tid) {
    float* As = sm;
    float* Bs = sm + 64 * APAD;
    int tx = tid & 15, ty = tid >> 4;

    u64 acc[8][4];
#pragma unroll
    for (int i = 0; i < 8; ++i)
#pragma unroll
        for (int jp = 0; jp < 4; ++jp) acc[i][jp] = 0ull;

    for (int kt = 0; kt < 4; ++kt) {
        int kb = kt * 32;
        __syncthreads();
#pragma unroll
        for (int r = 0; r < 4; ++r) {
            int idx = r * 128 + tid;
            int e = idx >> 3, c4 = idx & 7;
            int n = n0 + e;
            float4 v = make_float4(0.f, 0.f, 0.f, 0.f);
            if (n < NN) v = *(const float4*)&g_h[(size_t)n * 128 + kb + c4 * 4];
            *(float4*)&As[e * APAD + c4 * 4] = v;
        }
        fill_B(Bs, W, kb, tid);
        __syncthreads();
        mm_row(As, APAD, ty * 8, 0, Bs, tx, acc);
    }

    float bj[8];
#pragma unroll
    for (int q = 0; q < 8; ++q) bj[q] = bias ? bias[tx * 8 + q] : 0.f;
#pragma unroll
    for (int i = 0; i < 8; ++i) {
        int n = n0 + ty * 8 + i;
        if (n < NN) {
#pragma unroll
            for (int jp = 0; jp < 4; ++jp) {
                float2 c = unpack2(acc[i][jp]);
                c.x += bj[2 * jp]; c.y += bj[2 * jp + 1];
                *(float2*)&outp[(size_t)n * 128 + tx * 8 + 2 * jp] = c;
            }
        }
    }
}

__global__ __launch_bounds__(128, 4) void k_pq(const float* __restrict__ W1,
                                               const float* __restrict__ B1m) {
    extern __shared__ float sm[];
    int sel = blockIdx.y;
    gemm64(sel ? (W1 + 128 * 128) : W1, sel ? nullptr : B1m,
           sel ? g_Q : g_P, blockIdx.x * 64, sm, threadIdx.x);
}

__global__ __launch_bounds__(128, 4) void k_u(const float* __restrict__ Wa) {
    extern __shared__ float sm[];
    gemm64(Wa, nullptr, g_U, blockIdx.x * 64, sm, threadIdx.x);
}

// ---------------- segmented edge reduction ----------------
__device__ __forceinline__ void edge_acc(float4& a, float4 P4, float4 q, float4 r,
                                         float4 wc0, float4 wc1, float4 wc2) {
    a.x += fmaxf(P4.x + q.x + r.y * wc0.x + r.z * wc1.x + r.w * wc2.x, 0.f);
    a.y += fmaxf(P4.y + q.y + r.y * wc0.y + r.z * wc1.y + r.w * wc2.y, 0.f);
    a.z += fmaxf(P4.z + q.z + r.y * wc0.z + r.z * wc1.z + r.w * wc2.z, 0.f);
    a.w += fmaxf(P4.w + q.w + r.y * wc0.w + r.z * wc1.w + r.w * wc2.w, 0.f);
}

__global__ void k_edge_seg(const float* __restrict__ W1) {
    int wid = threadIdx.x >> 5, lane = threadIdx.x & 31;
    int n = blockIdx.x * 8 + wid;
    if (n >= NN) return;
    int c4 = lane * 4;
    float4 P4  = *(const float4*)&g_P[(size_t)n * 128 + c4];
    float4 wc0 = *(const float4*)&W1[(size_t)256 * 128 + c4];
    float4 wc1 = *(const float4*)&W1[(size_t)257 * 128 + c4];
    float4 wc2 = *(const float4*)&W1[(size_t)258 * 128 + c4];
    int start = g_off[n], deg = g_cnt[n];
    float4 a0 = make_float4(0.f, 0.f, 0.f, 0.f);
    float4 a1 = make_float4(0.f, 0.f, 0.f, 0.f);
    int i = 0;
    for (; i + 3 < deg; i += 4) {
        float4 r0 = g_rec[start + i];
        float4 r1 = g_rec[start + i + 1];
        float4 r2 = g_rec[start + i + 2];
        float4 r3 = g_rec[start + i + 3];
        float4 q0 = *(const float4*)&g_Q[(size_t)__float_as_int(r0.x) * 128 + c4];
        float4 q1 = *(const float4*)&g_Q[(size_t)__float_as_int(r1.x) * 128 + c4];
        float4 q2 = *(const float4*)&g_Q[(size_t)__float_as_int(r2.x) * 128 + c4];
        float4 q3 = *(const float4*)&g_Q[(size_t)__float_as_int(r3.x) * 128 + c4];
        edge_acc(a0, P4, q0, r0, wc0, wc1, wc2);
        edge_acc(a1, P4, q1, r1, wc0, wc1, wc2);
        edge_acc(a0, P4, q2, r2, wc0, wc1, wc2);
        edge_acc(a1, P4, q3, r3, wc0, wc1, wc2);
    }
    for (; i < deg; ++i) {
        float4 r0 = g_rec[start + i];
        float4 q0 = *(const float4*)&g_Q[(size_t)__float_as_int(r0.x) * 128 + c4];
        edge_acc(a0, P4, q0, r0, wc0, wc1, wc2);
    }
    float iv = g_inv[n];
    *(float4*)&g_agg[(size_t)n * 128 + c4] =
        make_float4((a0.x + a1.x) * iv, (a0.y + a1.y) * iv,
                    (a0.z + a1.z) * iv, (a0.w + a1.w) * iv);
}

// ---------------- update MLP: cp.async double-buffered ----------------
#define SM_UPD ((2 * 64 * APAD + 2 * 32 * 128 + 64 * TPAD) * 4)
__global__ __launch_bounds__(128, 2) void k_update(
    const float* __restrict__ B1, int layer,
    const float* __restrict__ W2, const float* __restrict__ B2,
    const float* __restrict__ lng, const float* __restrict__ lnb) {
    extern __shared__ float sm[];
    float* Asb[2] = { sm, sm + 64 * APAD };
    float* Bsb[2] = { sm + 2 * 64 * APAD, sm + 2 * 64 * APAD + 32 * 128 };
    float* Ts = sm + 2 * 64 * APAD + 2 * 32 * 128;
    __shared__ float s_flag[64];
    __shared__ float s_bc[128];

    int tid = threadIdx.x;
    int tx = tid & 15, ty = tid >> 4;
    int n0 = blockIdx.x * 64;
    const float* __restrict__ Wc = g_Wc[layer];

    if (tid < 64) {
        int n = n0 + tid;
        s_flag[tid] = (n < NN) ? g_flag[n] : 0.f;
    }
    s_bc[tid] = g_bc[layer][tid];

    u64 acc[8][4];
#pragma unroll
    for (int i = 0; i < 8; ++i)
#pragma unroll
        for (int jp = 0; jp < 4; ++jp) acc[i][jp] = 0ull;

    cp_A(Asb[0], g_agg, n0, 0, tid);
    cp_B(Bsb[0], Wc, 0, tid);
    CP_COMMIT();
#pragma unroll
    for (int kt = 0; kt < 4; ++kt) {
        if (kt < 3) {
            int nb = (kt + 1) & 1;
            cp_A(Asb[nb], g_agg, n0, (kt + 1) * 32, tid);
            cp_B(Bsb[nb], Wc, (kt + 1) * 32, tid);
            CP_COMMIT();
            CP_WAIT(1);
        } else {
            CP_WAIT(0);
        }
        __syncthreads();
        mm_row(Asb[kt & 1], APAD, ty * 8, 0, Bsb[kt & 1], tx, acc);
        __syncthreads();
    }

    {
        float bj[8], bc[8];
#pragma unroll
        for (int q = 0; q < 8; ++q) { bj[q] = B1[tx * 8 + q]; bc[q] = s_bc[tx * 8 + q]; }
#pragma unroll
        for (int i = 0; i < 8; ++i) {
            int e = ty * 8 + i;
            int n = n0 + e;
            float fz = s_flag[e];
#pragma unroll
            for (int jp = 0; jp < 4; ++jp) {
                float2 c = unpack2(acc[i][jp]);
                float u0 = 0.f, u1 = 0.f;
                if (n < NN) {
                    float2 uv = *(const float2*)&g_U[(size_t)n * 128 + tx * 8 + 2 * jp];
                    u0 = uv.x; u1 = uv.y;
                }
                c.x = fmaxf(c.x + u0 + bj[2 * jp]     + fz * bc[2 * jp],     0.f);
                c.y = fmaxf(c.y + u1 + bj[2 * jp + 1] + fz * bc[2 * jp + 1], 0.f);
                *(float2*)&Ts[e * TPAD + tx * 8 + 2 * jp] = c;
            }
        }
        __syncthreads();
    }

    u64 acc2[8][4];
#pragma unroll
    for (int i = 0; i < 8; ++i)
#pragma unroll
        for (int jp = 0; jp < 4; ++jp) acc2[i][jp] = 0ull;

    cp_B(Bsb[0], W2, 0, tid);
    CP_COMMIT();
#pragma unroll
    for (int kt = 0; kt < 4; ++kt) {
        if (kt < 3) {
            cp_B(Bsb[(kt + 1) & 1], W2, (kt + 1) * 32, tid);
            CP_COMMIT();
            CP_WAIT(1);
        } else {
            CP_WAIT(0);
        }
        __syncthreads();
        mm_row(Ts, TPAD, ty * 8, kt * 32, Bsb[kt & 1], tx, acc2);
        __syncthreads();
    }

    {
        float bj[8];
#pragma unroll
        for (int q = 0; q < 8; ++q) bj[q] = B2[tx * 8 + q];
#pragma unroll
        for (int i = 0; i < 8; ++i) {
            int e = ty * 8 + i;
            int n = n0 + e;
#pragma unroll
            for (int jp = 0; jp < 4; ++jp) {
                float2 c = unpack2(acc2[i][jp]);
                float h0 = 0.f, h1 = 0.f;
                if (n < NN) {
                    float2 hv = *(const float2*)&g_h[(size_t)n * 128 + tx * 8 + 2 * jp];
                    h0 = hv.x; h1 = hv.y;
                }
                c.x += bj[2 * jp] + h0;
                c.y += bj[2 * jp + 1] + h1;
                *(float2*)&Ts[e * TPAD + tx * 8 + 2 * jp] = c;
            }
        }
        __syncthreads();
    }

    {
        int wid = tid >> 5, lane = tid & 31;
        for (int rr = 0; rr < 16; ++rr) {
            int e = wid * 16 + rr;
            int n = n0 + e;
            float v0 = Ts[e * TPAD + lane];
            float v1 = Ts[e * TPAD + lane + 32];
            float v2 = Ts[e * TPAD + lane + 64];
            float v3 = Ts[e * TPAD + lane + 96];
            float s = v0 + v1 + v2 + v3;
#pragma unroll
            for (int o = 16; o > 0; o >>= 1) s += __shfl_xor_sync(0xffffffffu, s, o);
            float mu = s * (1.0f / 128.0f);
            float d0 = v0 - mu, d1 = v1 - mu, d2 = v2 - mu, d3 = v3 - mu;
            float q = d0 * d0 + d1 * d1 + d2 * d2 + d3 * d3;
#pragma unroll
            for (int o = 16; o > 0; o >>= 1) q += __shfl_xor_sync(0xffffffffu, q, o);
            float rs = rsqrtf(q * (1.0f / 128.0f) + 1e-5f);
            if (n < NN) {
                size_t base = (size_t)n * 128;
                g_h[base + lane]      = d0 * rs * lng[lane]      + lnb[lane];
                g_h[base + lane + 32] = d1 * rs * lng[lane + 32] + lnb[lane + 32];
                g_h[base + lane + 64] = d2 * rs * lng[lane + 64] + lnb[lane + 64];
                g_h[base + lane + 96] = d3 * rs * lng[lane + 96] + lnb[lane + 96];
            }
        }
    }
}

// ---------------- fused decoder ----------------
#define SM_DEC ((64 * TPAD + 32 * 128 + 128) * 4)
__global__ __launch_bounds__(128, 4) void k_dec(
    const float* __restrict__ w1, const float* __restrict__ b1,
    const float* __restrict__ w2, const float* __restrict__ b2,
    float* __restrict__ out) {
    extern __shared__ float sm[];
    float* Ts  = sm;
    float* Bs  = Ts + 64 * TPAD;
    float* sw2 = Bs + 32 * 128;
    int tid = threadIdx.x;
    int tx = tid & 15, ty = tid >> 4;
    int wid = tid >> 5, lane = tid & 31;
    int n0 = blockIdx.x * 64;

    sw2[tid] = w2[tid];
#pragma unroll
    for (int r = 0; r < 16; ++r) {
        int idx = r * 128 + tid;
        int e = idx >> 5, j4 = idx & 31;
        int n = n0 + e;
        float4 v = make_float4(0.f, 0.f, 0.f, 0.f);
        if (n < NN) v = *(const float4*)&g_h[(size_t)n * 128 + j4 * 4];
        *(float4*)&Ts[e * TPAD + j4 * 4] = v;
    }
    __syncthreads();

    u64 acc[8][4];
#pragma unroll
    for (int i = 0; i < 8; ++i)
#pragma unroll
        for (int jp = 0; jp < 4; ++jp) acc[i][jp] = 0ull;
    for (int kt = 0; kt < 4; ++kt) {
        __syncthreads();
        fill_B(Bs, w1, kt * 32, tid);
        __syncthreads();
        mm_row(Ts, TPAD, ty * 8, kt * 32, Bs, tx, acc);
    }
    float tv[8][8];
    {
        float bj[8];
#pragma unroll
        for (int q = 0; q < 8; ++q) bj[q] = b1[tx * 8 + q];
#pragma unroll
        for (int i = 0; i < 8; ++i)
#pragma unroll
            for (int jp = 0; jp < 4; ++jp) {
                float2 c = unpack2(acc[i][jp]);
                tv[i][2 * jp]     = fmaxf(c.x + bj[2 * jp], 0.f);
                tv[i][2 * jp + 1] = fmaxf(c.y + bj[2 * jp + 1], 0.f);
            }
    }
    __syncthreads();
#pragma unroll
    for (int i = 0; i < 8; ++i) {
        int e = ty * 8 + i;
#pragma unroll
        for (int q = 0; q < 8; ++q) Ts[e * TPAD + tx * 8 + q] = tv[i][q];
    }
    __syncthreads();

    for (int rr = 0; rr < 16; ++rr) {
        int e = wid * 16 + rr;
        int n = n0 + e;
        float4 t = *(const float4*)&Ts[e * TPAD + lane * 4];
        float4 w = *(const float4*)&sw2[lane * 4];
        float s = t.x * w.x + t.y * w.y + t.z * w.z + t.w * w.w;
#pragma unroll
        for (int o = 16; o > 0; o >>= 1) s += __shfl_xor_sync(0xffffffffu, s, o);
        if (lane == 0 && n < NN) out[n] = s + b2[0];
    }
}

// ---------------- stream/event singletons for fork-join ----------------
static cudaStream_t g_s2 = nullptr;
static cudaEvent_t  g_evF = nullptr, g_evU = nullptr;
static int g_sinit = 0;   // 0 = untried, 1 = ok, -1 = failed (fallback serial)

// ---------------- launch ----------------
extern "C" void kernel_launch(void* const* d_in, const int* in_sizes, int n_in,
                              void* d_out, int out_size) {
    const float* x      = (const float*)d_in[0];
    const int*   ei     = (const int*)  d_in[1];
    const float* eattr  = (const float*)d_in[2];
    const float* enc_w1 = (const float*)d_in[3];
    const float* enc_b1 = (const float*)d_in[4];
    const float* enc_w2 = (const float*)d_in[5];
    const float* enc_b2 = (const float*)d_in[6];
    const float* msg_w1 = (const float*)d_in[7];
    const float* msg_b1 = (const float*)d_in[8];
    const float* msg_w2 = (const float*)d_in[9];
    const float* msg_b2 = (const float*)d_in[10];
    const float* upd_w1 = (const float*)d_in[11];
    const float* upd_b1 = (const float*)d_in[12];
    const float* upd_w2 = (const float*)d_in[13];
    const float* upd_b2 = (const float*)d_in[14];
    const float* ln_g   = (const float*)d_in[15];
    const float* ln_b   = (const float*)d_in[16];
    const float* dec_w1 = (const float*)d_in[17];
    const float* dec_b1 = (const float*)d_in[18];
    const float* dec_w2 = (const float*)d_in[19];
    const float* dec_b2 = (const float*)d_in[20];
    float* out = (float*)d_out;

    cudaFuncSetAttribute(k_place_enc, cudaFuncAttributeMaxDynamicSharedMemorySize, SM_ENC);
    cudaFuncSetAttribute(k_pq,        cudaFuncAttributeMaxDynamicSharedMemorySize, SM_G);
    cudaFuncSetAttribute(k_u,         cudaFuncAttributeMaxDynamicSharedMemorySize, SM_G);
    cudaFuncSetAttribute(k_update,    cudaFuncAttributeMaxDynamicSharedMemorySize, SM_UPD);
    cudaFuncSetAttribute(k_dec,       cudaFuncAttributeMaxDynamicSharedMemorySize, SM_DEC);

    if (g_sinit == 0) {
        bool ok = (cudaStreamCreateWithFlags(&g_s2, cudaStreamNonBlocking) == cudaSuccess)
               && (cudaEventCreateWithFlags(&g_evF, cudaEventDisableTiming) == cudaSuccess)
               && (cudaEventCreateWithFlags(&g_evU, cudaEventDisableTiming) == cudaSuccess);
        g_sinit = ok ? 1 : -1;
    }
    bool fork = (g_sinit == 1);

    // degree count + Wc/bc precompute
    void* cntp = nullptr;
    cudaGetSymbolAddress(&cntp, g_cnt);
    cudaMemsetAsync(cntp, 0, NN * sizeof(int));
    k_count_fuse<<<CNT_BLKS + 258, 256>>>(ei, msg_w2, msg_b2, upd_w1);
    k_scan<<<1, 256>>>();
    // record placement + encoder
    k_place_enc<<<PLACE_BLKS + NB64, 128, SM_ENC>>>(ei, eattr, x,
                                                    enc_w1, enc_b1, enc_w2, enc_b2);

    for (int l = 0; l < 4; ++l) {
        const float* W1l = msg_w1 + (size_t)l * 259 * 128;
        const float* Wal = upd_w1 + (size_t)l * 256 * 128;
        if (fork) {
            // fork: U = h@Wa on side stream, overlapping pq + edge
            cudaEventRecord(g_evF, 0);
            cudaStreamWaitEvent(g_s2, g_evF, 0);
            k_u<<<NB64, 128, SM_G, g_s2>>>(Wal);
            cudaEventRecord(g_evU, g_s2);
            k_pq<<<dim3(NB64, 2), 128, SM_G>>>(W1l, msg_b1 + (size_t)l * 128);
            k_edge_seg<<<NN / 8, 256>>>(W1l);
            cudaStreamWaitEvent(0, g_evU, 0);
        } else {
            k_pq<<<dim3(NB64, 2), 128, SM_G>>>(W1l, msg_b1 + (size_t)l * 128);
            k_u<<<NB64, 128, SM_G>>>(Wal);
            k_edge_seg<<<NN / 8, 256>>>(W1l);
        }
        k_update<<<NB64, 128, SM_UPD>>>(
            upd_b1 + (size_t)l * 128, l,
            upd_w2 + (size_t)l * 128 * 128, upd_b2 + (size_t)l * 128,
            ln_g + (size_t)l * 128, ln_b + (size_t)l * 128);
    }

    k_dec<<<NB64, 128, SM_DEC>>>(dec_w1, dec_b1, dec_w2, dec_b2, out);
}